// round 15
// baseline (speedup 1.0000x reference)
#include <cuda_runtime.h>
#include <cuda_fp16.h>
#include <cstdint>

#define NMAX 50000
#define EMAX 800000
#define DDIM 128

// ---------------- static scratch (no allocation allowed) -------------------
__device__ float g_Wc[DDIM * DDIM];
__device__ float g_bc[DDIM];
__device__ int   g_degi[NMAX];       // zero-invariant: gather re-zeroes after use
__device__ int   g_off[NMAX];
__device__ int   g_rank[EMAX];       // per-edge rank within its destination bucket
__device__ int   g_bucket[EMAX];
__device__ int   g_bsum[64];
__device__ __align__(16) short  g_xq[(size_t)NMAX * DDIM];  // x*2048 int16 (gather)
__device__ __align__(16) __half g_xh[(size_t)NMAX * DDIM];  // x fp16 (GEMM A)
__device__ __align__(16) __half g_agh[(size_t)NMAX * DDIM]; // agg fp16 (GEMM A)
__device__ __align__(16) __half g_Bf[128 * 256];            // [W1;Wc]^T fp16 [N][K]

#define XQ_SCALE 2048.0f
#define XQ_INV   (1.0f / 2048.0f)

// ---------------- K1: hist+rank | wcbc | x-quantize (int16 + fp16) ----------
__global__ __launch_bounds__(256) void k1_kernel(
    const int* __restrict__ ecol, int E, int eb,
    const float* __restrict__ aggW, const float* __restrict__ aggb,
    const float* __restrict__ W,    const float* __restrict__ b,
    const float* __restrict__ x, int nquad)
{
    int bid = blockIdx.x;
    if (bid < eb) {
        int e = bid * 256 + threadIdx.x;
        if (e < E) g_rank[e] = atomicAdd(g_degi + ecol[e], 1);
    } else if (bid < eb + 64) {
        int k = (bid - eb) * 2 + (threadIdx.x >> 7);
        int n = threadIdx.x & 127;
        float acc = 0.f;
        #pragma unroll 8
        for (int j = 0; j < DDIM; j++)
            acc = fmaf(aggW[k * DDIM + j], W[(size_t)(DDIM + j) * DDIM + n], acc);
        g_Wc[k * DDIM + n] = acc;
        if (bid == eb && threadIdx.x < 128) {
            float bcv = b[n];
            #pragma unroll 8
            for (int j = 0; j < DDIM; j++)
                bcv = fmaf(aggb[j], W[(size_t)(DDIM + j) * DDIM + n], bcv);
            g_bc[n] = bcv;
        }
    } else {
        int q = (bid - eb - 64) * 256 + threadIdx.x;
        if (q < nquad) {
            size_t base = (size_t)q * 8;
            float4 v0 = *reinterpret_cast<const float4*>(x + base);
            float4 v1 = *reinterpret_cast<const float4*>(x + base + 4);
            short o[8];
            o[0] = (short)max(-32767, min(32767, __float2int_rn(v0.x * XQ_SCALE)));
            o[1] = (short)max(-32767, min(32767, __float2int_rn(v0.y * XQ_SCALE)));
            o[2] = (short)max(-32767, min(32767, __float2int_rn(v0.z * XQ_SCALE)));
            o[3] = (short)max(-32767, min(32767, __float2int_rn(v0.w * XQ_SCALE)));
            o[4] = (short)max(-32767, min(32767, __float2int_rn(v1.x * XQ_SCALE)));
            o[5] = (short)max(-32767, min(32767, __float2int_rn(v1.y * XQ_SCALE)));
            o[6] = (short)max(-32767, min(32767, __float2int_rn(v1.z * XQ_SCALE)));
            o[7] = (short)max(-32767, min(32767, __float2int_rn(v1.w * XQ_SCALE)));
            *reinterpret_cast<uint4*>(g_xq + base) = *reinterpret_cast<uint4*>(o);
            __half h[8];
            h[0] = __float2half_rn(v0.x); h[1] = __float2half_rn(v0.y);
            h[2] = __float2half_rn(v0.z); h[3] = __float2half_rn(v0.w);
            h[4] = __float2half_rn(v1.x); h[5] = __float2half_rn(v1.y);
            h[6] = __float2half_rn(v1.z); h[7] = __float2half_rn(v1.w);
            *reinterpret_cast<uint4*>(g_xh + base) = *reinterpret_cast<uint4*>(h);
        }
    }
}

// ---------------- scan1/scan2: two-phase parallel exclusive scan ------------
__global__ __launch_bounds__(1024) void scan1_kernel(int n)
{
    __shared__ int wsum[32];
    const int tid = threadIdx.x, lane = tid & 31, wid = tid >> 5;
    const int i = blockIdx.x * 1024 + tid;
    int v = (i < n) ? g_degi[i] : 0;
    int inc = v;
    #pragma unroll
    for (int o = 1; o < 32; o <<= 1) {
        int t = __shfl_up_sync(0xFFFFFFFFu, inc, o);
        if (lane >= o) inc += t;
    }
    if (lane == 31) wsum[wid] = inc;
    __syncthreads();
    if (wid == 0) {
        int w = wsum[lane];
        #pragma unroll
        for (int o = 1; o < 32; o <<= 1) {
            int t = __shfl_up_sync(0xFFFFFFFFu, w, o);
            if (lane >= o) w += t;
        }
        wsum[lane] = w;
    }
    __syncthreads();
    int excl = inc - v + (wid ? wsum[wid - 1] : 0);
    if (i < n) g_off[i] = excl;
    if (tid == 1023) g_bsum[blockIdx.x] = excl + v;
}

__global__ __launch_bounds__(1024) void scan2_kernel(int n)
{
    __shared__ int off_s;
    const int tid = threadIdx.x, lane = tid & 31;
    const int bid = blockIdx.x;
    if (tid < 32) {
        int o = 0;
        if (lane < bid) o = g_bsum[lane];
        if (lane + 32 < bid) o += g_bsum[lane + 32];
        #pragma unroll
        for (int s = 16; s > 0; s >>= 1)
            o += __shfl_xor_sync(0xFFFFFFFFu, o, s);
        if (lane == 0) off_s = o;
    }
    __syncthreads();
    int i = bid * 1024 + tid;
    if (i < n) g_off[i] += off_s;
}

// ---------------- K2: binfill (atomic-free) | B transpose + fp16 ------------
__global__ __launch_bounds__(256) void k2_kernel(
    const int* __restrict__ erow, const int* __restrict__ ecol, int E, int eb,
    const float* __restrict__ W)
{
    int bid = blockIdx.x;
    if (bid < eb) {
        int e = bid * 256 + threadIdx.x;
        if (e >= E) return;
        g_bucket[g_off[ecol[e]] + g_rank[e]] = erow[e];
    } else {
        int idx = (bid - eb) * 256 + threadIdx.x;
        if (idx >= 128 * 256) return;
        int n = idx >> 8, k = idx & 255;
        float v = (k < DDIM) ? W[(size_t)k * DDIM + n]
                             : g_Wc[(size_t)(k - DDIM) * DDIM + n];
        g_Bf[idx] = __float2half_rn(v);
    }
}

// ---------------- gather-mean: warp/node, unroll 8, fp16 output -------------
__global__ __launch_bounds__(256) void gather_kernel(int M)
{
    int w    = (blockIdx.x * blockDim.x + threadIdx.x) >> 5;
    int lane = threadIdx.x & 31;
    if (w >= M) return;
    int s = g_off[w];
    int d = g_degi[w];
    int a0 = 0, a1 = 0, a2 = 0, a3 = 0;
    int j = 0;
    for (; j + 8 <= d; j += 8) {
        int r[8];
        #pragma unroll
        for (int t = 0; t < 8; t++) r[t] = g_bucket[s + j + t];
        uint2 v[8];
        #pragma unroll
        for (int t = 0; t < 8; t++)
            v[t] = *reinterpret_cast<const uint2*>(g_xq + (size_t)r[t] * DDIM + lane * 4);
        #pragma unroll
        for (int t = 0; t < 8; t++) {
            a0 += (int)(short)(v[t].x);
            a1 += ((int)v[t].x >> 16);
            a2 += (int)(short)(v[t].y);
            a3 += ((int)v[t].y >> 16);
        }
    }
    for (; j < d; j++) {
        int r = g_bucket[s + j];
        uint2 v = *reinterpret_cast<const uint2*>(g_xq + (size_t)r * DDIM + lane * 4);
        a0 += (int)(short)(v.x);
        a1 += ((int)v.x >> 16);
        a2 += (int)(short)(v.y);
        a3 += ((int)v.y >> 16);
    }
    float rd = XQ_INV / fmaxf((float)d, 1.0f);
    __half h[4];
    h[0] = __float2half_rn((float)a0 * rd);
    h[1] = __float2half_rn((float)a1 * rd);
    h[2] = __float2half_rn((float)a2 * rd);
    h[3] = __float2half_rn((float)a3 * rd);
    *reinterpret_cast<uint2*>(g_agh + (size_t)w * DDIM + lane * 4) =
        *reinterpret_cast<uint2*>(h);
    if (lane == 0) g_degi[w] = 0;      // restore zero-invariant
}

// ---------------- GEMM + ReLU + LayerNorm (fp16, copy-only A fills) ---------
#define A_STRIDE_B 272
#define B_STRIDE_B 528
#define TILE_M    64
#define SM_BIAS   0
#define SM_GAMMA  512
#define SM_BETA   1024
#define SM_A      1536
#define SM_BF     (SM_A + TILE_M * A_STRIDE_B)      // 18944
#define SM_TOTAL  (SM_BF + 128 * B_STRIDE_B)        // 86528 B -> 2 CTAs/SM
#define SM_STAGE  SM_A

__device__ __forceinline__ uint32_t smem_u32(const void* p) {
    uint32_t a;
    asm("{ .reg .u64 t; cvta.to.shared.u64 t, %1; cvt.u32.u64 %0, t; }"
        : "=r"(a) : "l"(p));
    return a;
}
__device__ __forceinline__ void ldmx4(uint32_t* r, uint32_t addr) {
    asm volatile("ldmatrix.sync.aligned.m8n8.x4.shared.b16 {%0,%1,%2,%3}, [%4];"
                 : "=r"(r[0]), "=r"(r[1]), "=r"(r[2]), "=r"(r[3]) : "r"(addr));
}
__device__ __forceinline__ void mma_f16(float* c, const uint32_t* a, uint32_t b0, uint32_t b1) {
    asm volatile(
        "mma.sync.aligned.m16n8k16.row.col.f32.f16.f16.f32 "
        "{%0,%1,%2,%3}, {%4,%5,%6,%7}, {%8,%9}, {%0,%1,%2,%3};"
        : "+f"(c[0]), "+f"(c[1]), "+f"(c[2]), "+f"(c[3])
        : "r"(a[0]), "r"(a[1]), "r"(a[2]), "r"(a[3]), "r"(b0), "r"(b1));
}

__global__ __launch_bounds__(256, 2) void mma_gemm_kernel(
    const float* __restrict__ gamma,
    const float* __restrict__ beta,
    float* __restrict__ out,
    int M)
{
    extern __shared__ char smem[];
    const uint32_t sb = smem_u32(smem);
    const int tid  = threadIdx.x;
    const int wid  = tid >> 5;
    const int lane = tid & 31;
    const int base_row = blockIdx.x * TILE_M;
    const int warp_m = wid & 1;
    const int warp_n = wid >> 1;

    if (tid < 32) {
        reinterpret_cast<float4*>(smem + SM_BIAS)[tid]  =
            reinterpret_cast<const float4*>(g_bc)[tid];
        reinterpret_cast<float4*>(smem + SM_GAMMA)[tid] =
            reinterpret_cast<const float4*>(gamma)[tid];
        reinterpret_cast<float4*>(smem + SM_BETA)[tid]  =
            reinterpret_cast<const float4*>(beta)[tid];
    }
    #pragma unroll
    for (int i = 0; i < 16; i++) {
        int idx = tid + i * 256;
        int n = idx >> 5, q = idx & 31;
        *reinterpret_cast<uint4*>(smem + SM_BF + n * B_STRIDE_B + q * 16) =
            *reinterpret_cast<const uint4*>(g_Bf + n * 256 + q * 8);
    }

    auto fill_from = [&](const __half* __restrict__ src) {
        #pragma unroll
        for (int i = 0; i < 4; i++) {
            int idx = tid + i * 256;
            int row = idx >> 4;
            int q   = idx & 15;
            int grow = base_row + row;
            if (grow >= M) grow = M - 1;
            *reinterpret_cast<uint4*>(smem + SM_A + (uint32_t)row * A_STRIDE_B + (uint32_t)q * 16) =
                *reinterpret_cast<const uint4*>(src + (size_t)grow * DDIM + q * 8);
        }
    };

    fill_from(g_xh);
    __syncthreads();

    uint4 pre[4];
    #pragma unroll
    for (int i = 0; i < 4; i++) {
        int idx = tid + i * 256;
        int row = idx >> 4;
        int q   = idx & 15;
        int grow = base_row + row;
        if (grow >= M) grow = M - 1;
        pre[i] = *reinterpret_cast<const uint4*>(g_agh + (size_t)grow * DDIM + q * 8);
    }

    float acc[2][4][4];
    #pragma unroll
    for (int i = 0; i < 2; i++)
        #pragma unroll
        for (int j = 0; j < 4; j++)
            #pragma unroll
            for (int c = 0; c < 4; c++) acc[i][j][c] = 0.f;

    const int a_row_lo = (lane & 7) + ((lane >> 3) & 1) * 8;
    const int a_koff   = ((lane >> 4) & 1) * 8;
    const int b_nrow   = warp_n * 32 + (lane & 7) + ((lane >> 4) & 1) * 8;
    const int b_koff   = ((lane >> 3) & 1) * 8;

    auto compute_half = [&](int h) {
        #pragma unroll
        for (int kc = 0; kc < 8; kc++) {
            const int kA = kc * 16 + a_koff;
            const int kB = h * 128 + kc * 16 + b_koff;
            uint32_t ah[2][4];
            #pragma unroll
            for (int i = 0; i < 2; i++) {
                int row = warp_m * 32 + i * 16 + a_row_lo;
                ldmx4(ah[i], sb + SM_A + (uint32_t)row * A_STRIDE_B + (uint32_t)kA * 2);
            }
            uint32_t bf[2][4];
            #pragma unroll
            for (int p = 0; p < 2; p++) {
                uint32_t off = (uint32_t)(b_nrow + p * 16) * B_STRIDE_B + (uint32_t)kB * 2;
                ldmx4(bf[p], sb + SM_BF + off);
            }
            #pragma unroll
            for (int i = 0; i < 2; i++)
                #pragma unroll
                for (int p = 0; p < 2; p++) {
                    mma_f16(acc[i][2 * p],     ah[i], bf[p][0], bf[p][1]);
                    mma_f16(acc[i][2 * p + 1], ah[i], bf[p][2], bf[p][3]);
                }
        }
    };

    compute_half(0);
    __syncthreads();

    #pragma unroll
    for (int i = 0; i < 4; i++) {
        int idx = tid + i * 256;
        int row = idx >> 4;
        int q   = idx & 15;
        *reinterpret_cast<uint4*>(smem + SM_A + (uint32_t)row * A_STRIDE_B + (uint32_t)q * 16) = pre[i];
    }
    __syncthreads();
    compute_half(1);
    __syncthreads();

    float* stg = reinterpret_cast<float*>(smem + SM_STAGE);
    #pragma unroll
    for (int i = 0; i < 2; i++) {
        int row0 = warp_m * 32 + i * 16 + (lane >> 2);
        #pragma unroll
        for (int j = 0; j < 4; j++) {
            int col = warp_n * 32 + j * 8 + (lane & 3) * 2;
            *reinterpret_cast<float2*>(stg + row0 * 132 + col) =
                make_float2(acc[i][j][0], acc[i][j][1]);
            *reinterpret_cast<float2*>(stg + (row0 + 8) * 132 + col) =
                make_float2(acc[i][j][2], acc[i][j][3]);
        }
    }
    __syncthreads();

    float4 b4 = *reinterpret_cast<const float4*>(smem + SM_BIAS  + lane * 16);
    float4 g4 = *reinterpret_cast<const float4*>(smem + SM_GAMMA + lane * 16);
    float4 t4 = *reinterpret_cast<const float4*>(smem + SM_BETA  + lane * 16);
    #pragma unroll
    for (int ii = 0; ii < 8; ii++) {
        int r = wid * 8 + ii;
        int grow = base_row + r;
        if (grow >= M) continue;
        float4 v = *reinterpret_cast<const float4*>(stg + r * 132 + lane * 4);
        v.x = fmaxf(v.x + b4.x, 0.f);
        v.y = fmaxf(v.y + b4.y, 0.f);
        v.z = fmaxf(v.z + b4.z, 0.f);
        v.w = fmaxf(v.w + b4.w, 0.f);
        float s  = v.x + v.y + v.z + v.w;
        float sq = v.x * v.x + v.y * v.y + v.z * v.z + v.w * v.w;
        #pragma unroll
        for (int o = 16; o > 0; o >>= 1) {
            s  += __shfl_xor_sync(0xFFFFFFFFu, s, o);
            sq += __shfl_xor_sync(0xFFFFFFFFu, sq, o);
        }
        float mean = s * (1.0f / DDIM);
        float var  = sq * (1.0f / DDIM) - mean * mean;
        float rstd = rsqrtf(var + 1e-5f);
        float4 o;
        o.x = (v.x - mean) * rstd * g4.x + t4.x;
        o.y = (v.y - mean) * rstd * g4.y + t4.y;
        o.z = (v.z - mean) * rstd * g4.z + t4.z;
        o.w = (v.w - mean) * rstd * g4.w + t4.w;
        *reinterpret_cast<float4*>(out + (size_t)grow * DDIM + lane * 4) = o;
    }
}

// ---------------------------------------------------------------------------
extern "C" void kernel_launch(void* const* d_in, const int* in_sizes, int n_in,
                              void* d_out, int out_size)
{
    const float* x     = (const float*)d_in[0];
    const int*   ei    = (const int*)d_in[1];
    const float* aggW  = (const float*)d_in[2];
    const float* aggb  = (const float*)d_in[3];
    const float* W     = (const float*)d_in[4];
    const float* b     = (const float*)d_in[5];
    const float* gamma = (const float*)d_in[6];
    const float* beta  = (const float*)d_in[7];
    float* out = (float*)d_out;

    const int E = in_sizes[1] / 2;
    const int M = in_sizes[0] / DDIM;

    cudaFuncSetAttribute(mma_gemm_kernel,
                         cudaFuncAttributeMaxDynamicSharedMemorySize, SM_TOTAL);

    const int* erow = ei;
    const int* ecol = ei + E;
    const int eb = (E + 255) / 256;
    const int nquad = (M * DDIM) / 8;
    const int pb = (nquad + 255) / 256;
    const int bb = (128 * 256 + 255) / 256;
    const int sbk = (M + 1023) / 1024;

    k1_kernel<<<eb + 64 + pb, 256>>>(ecol, E, eb, aggW, aggb, W, b, x, nquad);
    scan1_kernel<<<sbk, 1024>>>(M);
    scan2_kernel<<<sbk, 1024>>>(M);
    k2_kernel<<<eb + bb, 256>>>(erow, ecol, E, eb, W);
    gather_kernel<<<(M * 32 + 255) / 256, 256>>>(M);
    mma_gemm_kernel<<<(M + TILE_M - 1) / TILE_M, 256, SM_TOTAL>>>(gamma, beta, out, M);
}

// round 16
// speedup vs baseline: 1.0545x; 1.0545x over previous
#include <cuda_runtime.h>
#include <cuda_fp16.h>
#include <cstdint>

#define NMAX 50000
#define EMAX 800000
#define DDIM 128

// ---------------- static scratch (no allocation allowed) -------------------
__device__ float g_Wc[DDIM * DDIM];
__device__ float g_bc[DDIM];
__device__ int   g_degi[NMAX];       // zero-invariant: gather re-zeroes after use
__device__ int   g_off[NMAX];
__device__ int   g_cur[NMAX];
__device__ int   g_bucket[EMAX];
__device__ int   g_bsum[64];
__device__ __align__(16) __half g_xh[(size_t)NMAX * DDIM];  // x fp16 (gather + GEMM A)
__device__ __align__(16) __half g_agh[(size_t)NMAX * DDIM]; // agg fp16 (GEMM A)
__device__ __align__(16) __half g_Bf[128 * 256];            // [W1;Wc]^T fp16 [N][K]

// ---------------- K1: hist(RED) | wcbc | x->fp16 ----------------------------
__global__ __launch_bounds__(256) void k1_kernel(
    const int* __restrict__ ecol, int E, int eb,
    const float* __restrict__ aggW, const float* __restrict__ aggb,
    const float* __restrict__ W,    const float* __restrict__ b,
    const float* __restrict__ x, int nquad)
{
    int bid = blockIdx.x;
    if (bid < eb) {
        int e = bid * 256 + threadIdx.x;
        if (e < E) atomicAdd(g_degi + ecol[e], 1);   // return unused -> RED
    } else if (bid < eb + 64) {
        int k = (bid - eb) * 2 + (threadIdx.x >> 7);
        int n = threadIdx.x & 127;
        float acc = 0.f;
        #pragma unroll 8
        for (int j = 0; j < DDIM; j++)
            acc = fmaf(aggW[k * DDIM + j], W[(size_t)(DDIM + j) * DDIM + n], acc);
        g_Wc[k * DDIM + n] = acc;
        if (bid == eb && threadIdx.x < 128) {
            float bcv = b[n];
            #pragma unroll 8
            for (int j = 0; j < DDIM; j++)
                bcv = fmaf(aggb[j], W[(size_t)(DDIM + j) * DDIM + n], bcv);
            g_bc[n] = bcv;
        }
    } else {
        int q = (bid - eb - 64) * 256 + threadIdx.x;
        if (q < nquad) {
            size_t base = (size_t)q * 8;
            float4 v0 = *reinterpret_cast<const float4*>(x + base);
            float4 v1 = *reinterpret_cast<const float4*>(x + base + 4);
            __half h[8];
            h[0] = __float2half_rn(v0.x); h[1] = __float2half_rn(v0.y);
            h[2] = __float2half_rn(v0.z); h[3] = __float2half_rn(v0.w);
            h[4] = __float2half_rn(v1.x); h[5] = __float2half_rn(v1.y);
            h[6] = __float2half_rn(v1.z); h[7] = __float2half_rn(v1.w);
            *reinterpret_cast<uint4*>(g_xh + base) = *reinterpret_cast<uint4*>(h);
        }
    }
}

// ---------------- scan1/scan2: two-phase parallel exclusive scan ------------
__global__ __launch_bounds__(1024) void scan1_kernel(int n)
{
    __shared__ int wsum[32];
    const int tid = threadIdx.x, lane = tid & 31, wid = tid >> 5;
    const int i = blockIdx.x * 1024 + tid;
    int v = (i < n) ? g_degi[i] : 0;
    int inc = v;
    #pragma unroll
    for (int o = 1; o < 32; o <<= 1) {
        int t = __shfl_up_sync(0xFFFFFFFFu, inc, o);
        if (lane >= o) inc += t;
    }
    if (lane == 31) wsum[wid] = inc;
    __syncthreads();
    if (wid == 0) {
        int w = wsum[lane];
        #pragma unroll
        for (int o = 1; o < 32; o <<= 1) {
            int t = __shfl_up_sync(0xFFFFFFFFu, w, o);
            if (lane >= o) w += t;
        }
        wsum[lane] = w;
    }
    __syncthreads();
    int excl = inc - v + (wid ? wsum[wid - 1] : 0);
    if (i < n) g_off[i] = excl;
    if (tid == 1023) g_bsum[blockIdx.x] = excl + v;
}

__global__ __launch_bounds__(1024) void scan2_kernel(int n)
{
    __shared__ int off_s;
    const int tid = threadIdx.x, lane = tid & 31;
    const int bid = blockIdx.x;
    if (tid < 32) {
        int o = 0;
        if (lane < bid) o = g_bsum[lane];
        if (lane + 32 < bid) o += g_bsum[lane + 32];
        #pragma unroll
        for (int s = 16; s > 0; s >>= 1)
            o += __shfl_xor_sync(0xFFFFFFFFu, o, s);
        if (lane == 0) off_s = o;
    }
    __syncthreads();
    int i = bid * 1024 + tid;
    if (i < n) {
        int v = g_off[i] + off_s;
        g_off[i] = v;
        g_cur[i] = v;
    }
}

// ---------------- K2: binfill | B transpose + fp16 convert ------------------
__global__ __launch_bounds__(256) void k2_kernel(
    const int* __restrict__ erow, const int* __restrict__ ecol, int E, int eb,
    const float* __restrict__ W)
{
    int bid = blockIdx.x;
    if (bid < eb) {
        int e = bid * 256 + threadIdx.x;
        if (e >= E) return;
        int p = atomicAdd(g_cur + ecol[e], 1);
        g_bucket[p] = erow[e];
    } else {
        int idx = (bid - eb) * 256 + threadIdx.x;
        if (idx >= 128 * 256) return;
        int n = idx >> 8, k = idx & 255;
        float v = (k < DDIM) ? W[(size_t)k * DDIM + n]
                             : g_Wc[(size_t)(k - DDIM) * DDIM + n];
        g_Bf[idx] = __float2half_rn(v);
    }
}

// ---------------- gather-mean: warp/node from fp16, fp32 accum --------------
__global__ __launch_bounds__(256) void gather_kernel(int M)
{
    int w    = (blockIdx.x * blockDim.x + threadIdx.x) >> 5;
    int lane = threadIdx.x & 31;
    if (w >= M) return;
    int s = g_off[w];
    int d = g_degi[w];
    float a0 = 0.f, a1 = 0.f, a2 = 0.f, a3 = 0.f;
    int j = 0;
    for (; j + 8 <= d; j += 8) {              // 8 neighbors in flight
        int r[8];
        #pragma unroll
        for (int t = 0; t < 8; t++) r[t] = g_bucket[s + j + t];
        uint2 v[8];
        #pragma unroll
        for (int t = 0; t < 8; t++)
            v[t] = *reinterpret_cast<const uint2*>(g_xh + (size_t)r[t] * DDIM + lane * 4);
        #pragma unroll
        for (int t = 0; t < 8; t++) {
            float2 f0 = __half22float2(*reinterpret_cast<__half2*>(&v[t].x));
            float2 f1 = __half22float2(*reinterpret_cast<__half2*>(&v[t].y));
            a0 += f0.x; a1 += f0.y; a2 += f1.x; a3 += f1.y;
        }
    }
    for (; j < d; j++) {
        int r = g_bucket[s + j];
        uint2 v = *reinterpret_cast<const uint2*>(g_xh + (size_t)r * DDIM + lane * 4);
        float2 f0 = __half22float2(*reinterpret_cast<__half2*>(&v.x));
        float2 f1 = __half22float2(*reinterpret_cast<__half2*>(&v.y));
        a0 += f0.x; a1 += f0.y; a2 += f1.x; a3 += f1.y;
    }
    float rd = 1.0f / fmaxf((float)d, 1.0f);
    __half h[4];
    h[0] = __float2half_rn(a0 * rd);
    h[1] = __float2half_rn(a1 * rd);
    h[2] = __float2half_rn(a2 * rd);
    h[3] = __float2half_rn(a3 * rd);
    *reinterpret_cast<uint2*>(g_agh + (size_t)w * DDIM + lane * 4) =
        *reinterpret_cast<uint2*>(h);
    if (lane == 0) g_degi[w] = 0;      // restore zero-invariant
}

// ---------------- GEMM + ReLU + LayerNorm (fp16, copy-only A fills) ---------
#define A_STRIDE_B 272
#define B_STRIDE_B 528
#define TILE_M    64
#define SM_BIAS   0
#define SM_GAMMA  512
#define SM_BETA   1024
#define SM_A      1536
#define SM_BF     (SM_A + TILE_M * A_STRIDE_B)      // 18944
#define SM_TOTAL  (SM_BF + 128 * B_STRIDE_B)        // 86528 B -> 2 CTAs/SM
#define SM_STAGE  SM_A

__device__ __forceinline__ uint32_t smem_u32(const void* p) {
    uint32_t a;
    asm("{ .reg .u64 t; cvta.to.shared.u64 t, %1; cvt.u32.u64 %0, t; }"
        : "=r"(a) : "l"(p));
    return a;
}
__device__ __forceinline__ void ldmx4(uint32_t* r, uint32_t addr) {
    asm volatile("ldmatrix.sync.aligned.m8n8.x4.shared.b16 {%0,%1,%2,%3}, [%4];"
                 : "=r"(r[0]), "=r"(r[1]), "=r"(r[2]), "=r"(r[3]) : "r"(addr));
}
__device__ __forceinline__ void mma_f16(float* c, const uint32_t* a, uint32_t b0, uint32_t b1) {
    asm volatile(
        "mma.sync.aligned.m16n8k16.row.col.f32.f16.f16.f32 "
        "{%0,%1,%2,%3}, {%4,%5,%6,%7}, {%8,%9}, {%0,%1,%2,%3};"
        : "+f"(c[0]), "+f"(c[1]), "+f"(c[2]), "+f"(c[3])
        : "r"(a[0]), "r"(a[1]), "r"(a[2]), "r"(a[3]), "r"(b0), "r"(b1));
}

__global__ __launch_bounds__(256, 2) void mma_gemm_kernel(
    const float* __restrict__ gamma,
    const float* __restrict__ beta,
    float* __restrict__ out,
    int M)
{
    extern __shared__ char smem[];
    const uint32_t sb = smem_u32(smem);
    const int tid  = threadIdx.x;
    const int wid  = tid >> 5;
    const int lane = tid & 31;
    const int base_row = blockIdx.x * TILE_M;
    const int warp_m = wid & 1;
    const int warp_n = wid >> 1;

    if (tid < 32) {
        reinterpret_cast<float4*>(smem + SM_BIAS)[tid]  =
            reinterpret_cast<const float4*>(g_bc)[tid];
        reinterpret_cast<float4*>(smem + SM_GAMMA)[tid] =
            reinterpret_cast<const float4*>(gamma)[tid];
        reinterpret_cast<float4*>(smem + SM_BETA)[tid]  =
            reinterpret_cast<const float4*>(beta)[tid];
    }
    #pragma unroll
    for (int i = 0; i < 16; i++) {
        int idx = tid + i * 256;
        int n = idx >> 5, q = idx & 31;
        *reinterpret_cast<uint4*>(smem + SM_BF + n * B_STRIDE_B + q * 16) =
            *reinterpret_cast<const uint4*>(g_Bf + n * 256 + q * 8);
    }

    auto fill_from = [&](const __half* __restrict__ src) {
        #pragma unroll
        for (int i = 0; i < 4; i++) {
            int idx = tid + i * 256;
            int row = idx >> 4;
            int q   = idx & 15;
            int grow = base_row + row;
            if (grow >= M) grow = M - 1;
            *reinterpret_cast<uint4*>(smem + SM_A + (uint32_t)row * A_STRIDE_B + (uint32_t)q * 16) =
                *reinterpret_cast<const uint4*>(src + (size_t)grow * DDIM + q * 8);
        }
    };

    fill_from(g_xh);
    __syncthreads();

    uint4 pre[4];
    #pragma unroll
    for (int i = 0; i < 4; i++) {
        int idx = tid + i * 256;
        int row = idx >> 4;
        int q   = idx & 15;
        int grow = base_row + row;
        if (grow >= M) grow = M - 1;
        pre[i] = *reinterpret_cast<const uint4*>(g_agh + (size_t)grow * DDIM + q * 8);
    }

    float acc[2][4][4];
    #pragma unroll
    for (int i = 0; i < 2; i++)
        #pragma unroll
        for (int j = 0; j < 4; j++)
            #pragma unroll
            for (int c = 0; c < 4; c++) acc[i][j][c] = 0.f;

    const int a_row_lo = (lane & 7) + ((lane >> 3) & 1) * 8;
    const int a_koff   = ((lane >> 4) & 1) * 8;
    const int b_nrow   = warp_n * 32 + (lane & 7) + ((lane >> 4) & 1) * 8;
    const int b_koff   = ((lane >> 3) & 1) * 8;

    auto compute_half = [&](int h) {
        #pragma unroll
        for (int kc = 0; kc < 8; kc++) {
            const int kA = kc * 16 + a_koff;
            const int kB = h * 128 + kc * 16 + b_koff;
            uint32_t ah[2][4];
            #pragma unroll
            for (int i = 0; i < 2; i++) {
                int row = warp_m * 32 + i * 16 + a_row_lo;
                ldmx4(ah[i], sb + SM_A + (uint32_t)row * A_STRIDE_B + (uint32_t)kA * 2);
            }
            uint32_t bf[2][4];
            #pragma unroll
            for (int p = 0; p < 2; p++) {
                uint32_t off = (uint32_t)(b_nrow + p * 16) * B_STRIDE_B + (uint32_t)kB * 2;
                ldmx4(bf[p], sb + SM_BF + off);
            }
            #pragma unroll
            for (int i = 0; i < 2; i++)
                #pragma unroll
                for (int p = 0; p < 2; p++) {
                    mma_f16(acc[i][2 * p],     ah[i], bf[p][0], bf[p][1]);
                    mma_f16(acc[i][2 * p + 1], ah[i], bf[p][2], bf[p][3]);
                }
        }
    };

    compute_half(0);
    __syncthreads();

    #pragma unroll
    for (int i = 0; i < 4; i++) {
        int idx = tid + i * 256;
        int row = idx >> 4;
        int q   = idx & 15;
        *reinterpret_cast<uint4*>(smem + SM_A + (uint32_t)row * A_STRIDE_B + (uint32_t)q * 16) = pre[i];
    }
    __syncthreads();
    compute_half(1);
    __syncthreads();

    float* stg = reinterpret_cast<float*>(smem + SM_STAGE);
    #pragma unroll
    for (int i = 0; i < 2; i++) {
        int row0 = warp_m * 32 + i * 16 + (lane >> 2);
        #pragma unroll
        for (int j = 0; j < 4; j++) {
            int col = warp_n * 32 + j * 8 + (lane & 3) * 2;
            *reinterpret_cast<float2*>(stg + row0 * 132 + col) =
                make_float2(acc[i][j][0], acc[i][j][1]);
            *reinterpret_cast<float2*>(stg + (row0 + 8) * 132 + col) =
                make_float2(acc[i][j][2], acc[i][j][3]);
        }
    }
    __syncthreads();

    float4 b4 = *reinterpret_cast<const float4*>(smem + SM_BIAS  + lane * 16);
    float4 g4 = *reinterpret_cast<const float4*>(smem + SM_GAMMA + lane * 16);
    float4 t4 = *reinterpret_cast<const float4*>(smem + SM_BETA  + lane * 16);
    #pragma unroll
    for (int ii = 0; ii < 8; ii++) {
        int r = wid * 8 + ii;
        int grow = base_row + r;
        if (grow >= M) continue;
        float4 v = *reinterpret_cast<const float4*>(stg + r * 132 + lane * 4);
        v.x = fmaxf(v.x + b4.x, 0.f);
        v.y = fmaxf(v.y + b4.y, 0.f);
        v.z = fmaxf(v.z + b4.z, 0.f);
        v.w = fmaxf(v.w + b4.w, 0.f);
        float s  = v.x + v.y + v.z + v.w;
        float sq = v.x * v.x + v.y * v.y + v.z * v.z + v.w * v.w;
        #pragma unroll
        for (int o = 16; o > 0; o >>= 1) {
            s  += __shfl_xor_sync(0xFFFFFFFFu, s, o);
            sq += __shfl_xor_sync(0xFFFFFFFFu, sq, o);
        }
        float mean = s * (1.0f / DDIM);
        float var  = sq * (1.0f / DDIM) - mean * mean;
        float rstd = rsqrtf(var + 1e-5f);
        float4 o;
        o.x = (v.x - mean) * rstd * g4.x + t4.x;
        o.y = (v.y - mean) * rstd * g4.y + t4.y;
        o.z = (v.z - mean) * rstd * g4.z + t4.z;
        o.w = (v.w - mean) * rstd * g4.w + t4.w;
        *reinterpret_cast<float4*>(out + (size_t)grow * DDIM + lane * 4) = o;
    }
}

// ---------------------------------------------------------------------------
extern "C" void kernel_launch(void* const* d_in, const int* in_sizes, int n_in,
                              void* d_out, int out_size)
{
    const float* x     = (const float*)d_in[0];
    const int*   ei    = (const int*)d_in[1];
    const float* aggW  = (const float*)d_in[2];
    const float* aggb  = (const float*)d_in[3];
    const float* W     = (const float*)d_in[4];
    const float* b     = (const float*)d_in[5];
    const float* gamma = (const float*)d_in[6];
    const float* beta  = (const float*)d_in[7];
    float* out = (float*)d_out;

    const int E = in_sizes[1] / 2;
    const int M = in_sizes[0] / DDIM;

    cudaFuncSetAttribute(mma_gemm_kernel,
                         cudaFuncAttributeMaxDynamicSharedMemorySize, SM_TOTAL);

    const int* erow = ei;
    const int* ecol = ei + E;
    const int eb = (E + 255) / 256;
    const int nquad = (M * DDIM) / 8;
    const int pb = (nquad + 255) / 256;
    const int bb = (128 * 256 + 255) / 256;
    const int sbk = (M + 1023) / 1024;

    k1_kernel<<<eb + 64 + pb, 256>>>(ecol, E, eb, aggW, aggb, W, b, x, nquad);
    scan1_kernel<<<sbk, 1024>>>(M);
    scan2_kernel<<<sbk, 1024>>>(M);
    k2_kernel<<<eb + bb, 256>>>(erow, ecol, E, eb, W);
    gather_kernel<<<(M * 32 + 255) / 256, 256>>>(M);
    mma_gemm_kernel<<<(M + TILE_M - 1) / TILE_M, 256, SM_TOTAL>>>(gamma, beta, out, M);
}